// round 1
// baseline (speedup 1.0000x reference)
#include <cuda_runtime.h>

// Problem constants (fixed by the dataset)
#define BB    64      // batch
#define INX   1024    // input_size
#define OUTX  1024    // output_size
#define DM    64      // D_MODEL
#define XKS   32
#define YKS   32
#define HID   256
#define GX    32      // gen_x
#define GY    32      // gen_y
#define YSPLIT 8      // split of the y-loop in the reduction kernel

// Scratch (static device globals -- no allocation allowed)
__device__ float g_PX[GX][HID];        // pe_x(j)@W1[0:64] + b1
__device__ float g_PY[GY][HID];        // pe_y(y)@W1[64:128]
__device__ float g_PEW[GX][HID];       // pe_b(y)@Wb1[32:96] + bb1
__device__ float g_A[BB][GY][HID];     // PX[j] + xchunk(b,j)@W1[128:160]
__device__ float g_U[BB][YSPLIT][HID]; // partial u sums
__device__ float g_S[BB];              // sum_i x[b,i]

// Accurate-enough tanh independent of fast-math flags:
// tanh(x) = (e^{2x}-1)/(e^{2x}+1), clamped. abs err ~1e-7.
__device__ __forceinline__ float fast_tanh(float x) {
    x = fminf(9.0f, fmaxf(-9.0f, x));
    float e = __expf(2.0f * x);
    return (e - 1.0f) / (e + 1.0f);
}

// ---------------------------------------------------------------------------
// K1: batch-independent tables. grid (32, 3), 256 threads.
//  blockIdx.y==0 : g_PX[p][c]  = b1[c]  + sum_d pe(p,d)*W1[d][c]
//  blockIdx.y==1 : g_PY[p][c]  =          sum_d pe(p,d)*W1[64+d][c]
//  blockIdx.y==2 : g_PEW[p][c] = bb1[c] + sum_d pe(p,d)*Wb1[32+d][c]
// ---------------------------------------------------------------------------
__global__ void k_tables(const float* __restrict__ W1, const float* __restrict__ b1,
                         const float* __restrict__ Wb1, const float* __restrict__ bb1) {
    int p     = blockIdx.x;
    int which = blockIdx.y;
    int c     = threadIdx.x;
    __shared__ float pe[DM];
    if (c < DM) {
        int i = c >> 1;
        // inv_freq = 10000^(-i/32) = exp(-i*ln(10000)/32)
        float f = expf(-(float)i * (9.210340371976184f / 32.0f));
        float ang = (float)p * f;
        pe[c] = (c & 1) ? cosf(ang) : sinf(ang);
    }
    __syncthreads();
    float acc;
    if (which == 0) {
        acc = b1[c];
        #pragma unroll 8
        for (int d = 0; d < DM; ++d) acc += pe[d] * W1[d * HID + c];
        g_PX[p][c] = acc;
    } else if (which == 1) {
        acc = 0.0f;
        #pragma unroll 8
        for (int d = 0; d < DM; ++d) acc += pe[d] * W1[(DM + d) * HID + c];
        g_PY[p][c] = acc;
    } else {
        acc = bb1[c];
        #pragma unroll 8
        for (int d = 0; d < DM; ++d) acc += pe[d] * Wb1[(YKS + d) * HID + c];
        g_PEW[p][c] = acc;
    }
}

// ---------------------------------------------------------------------------
// K2: A[b][j][c] = PX[j][c] + sum_k x[b, 32j+k]*W1[128+k][c]; also S[b].
// grid (64, 32), 256 threads.
// ---------------------------------------------------------------------------
__global__ void k_A(const float* __restrict__ x, const float* __restrict__ W1) {
    int b = blockIdx.x, j = blockIdx.y;
    int c = threadIdx.x;
    __shared__ float xs[XKS];
    if (c < XKS) xs[c] = x[b * INX + j * XKS + c];
    __syncthreads();
    float acc = g_PX[j][c];
    #pragma unroll
    for (int k = 0; k < XKS; ++k) acc += xs[k] * W1[(2 * DM + k) * HID + c];
    g_A[b][j][c] = acc;

    if (j == 0) {  // compute S[b] once per batch (j uniform per block)
        float s = 0.0f;
        for (int t = c; t < INX; t += HID) s += x[b * INX + t];
        __shared__ float red[HID];
        red[c] = s;
        __syncthreads();
        for (int st = HID / 2; st > 0; st >>= 1) {
            if (c < st) red[c] += red[c + st];
            __syncthreads();
        }
        if (c == 0) g_S[b] = red[0];
    }
}

// ---------------------------------------------------------------------------
// K3 (dominant): partial u[b][yg][c] = sum over y in [4yg,4yg+4), j in [0,32)
//   of x[b, 32y+j] * tanh(A[b][j][c] + PY[y][c]).
// grid (64, 8), 256 threads. A row cached in 32 registers per thread.
// ---------------------------------------------------------------------------
__global__ void k_U(const float* __restrict__ x) {
    int b = blockIdx.x, yg = blockIdx.y;
    int c = threadIdx.x;
    __shared__ float xs[128];
    int base = b * INX + yg * 128;
    if (c < 128) xs[c] = x[base + c];
    __syncthreads();

    float a[GY];
    #pragma unroll
    for (int jj = 0; jj < GY; ++jj) a[jj] = g_A[b][jj][c];

    float u = 0.0f;
    #pragma unroll
    for (int y4 = 0; y4 < 4; ++y4) {
        float py = g_PY[yg * 4 + y4][c];
        #pragma unroll
        for (int jj = 0; jj < GY; ++jj) {
            u += xs[y4 * 32 + jj] * fast_tanh(a[jj] + py);
        }
    }
    g_U[b][yg][c] = u;
}

// ---------------------------------------------------------------------------
// K4: out[b][o] = sum_c u[b][c]*W2[c][o] + S[b]*b2[o].
// grid (64), 256 threads; each thread handles 4 outputs (coalesced).
// ---------------------------------------------------------------------------
__global__ void k_out(const float* __restrict__ W2, const float* __restrict__ b2,
                      float* __restrict__ out) {
    int b = blockIdx.x;
    int c = threadIdx.x;
    __shared__ float us[HID];
    float u = 0.0f;
    #pragma unroll
    for (int p = 0; p < YSPLIT; ++p) u += g_U[b][p][c];
    us[c] = u;
    __syncthreads();

    float sb = g_S[b];
    float a0 = sb * b2[c];
    float a1 = sb * b2[c + 256];
    float a2 = sb * b2[c + 512];
    float a3 = sb * b2[c + 768];
    #pragma unroll 4
    for (int cc = 0; cc < HID; ++cc) {
        float uv = us[cc];
        const float* w = W2 + cc * OUTX;
        a0 += uv * w[c];
        a1 += uv * w[c + 256];
        a2 += uv * w[c + 512];
        a3 += uv * w[c + 768];
    }
    float* orow = out + b * OUTX;
    orow[c]       = a0;
    orow[c + 256] = a1;
    orow[c + 512] = a2;
    orow[c + 768] = a3;
}

// ---------------------------------------------------------------------------
// K5: bias hypernetwork, added in place.
// grid (64, 32), 256 threads.
//   hb[c] = tanh(PEW[y][c] + sum_k out[b,32y+k]*Wb1[k][c])
//   bias[o] = bb2[o] + sum_c hb[c]*Wb2[c][o];  out[b,32y+o] += bias[o]
// ---------------------------------------------------------------------------
__global__ void k_bias(const float* __restrict__ Wb1, const float* __restrict__ Wb2,
                       const float* __restrict__ bb2, float* __restrict__ out) {
    int b = blockIdx.x, y = blockIdx.y;
    int t = threadIdx.x;
    __shared__ float oc[YKS];
    __shared__ float hb[HID];
    __shared__ float part[8][YKS];
    float* orow = out + b * OUTX + y * YKS;
    if (t < YKS) oc[t] = orow[t];
    __syncthreads();

    float acc = g_PEW[y][t];
    #pragma unroll
    for (int k = 0; k < YKS; ++k) acc += oc[k] * Wb1[k * HID + t];
    hb[t] = fast_tanh(acc);
    __syncthreads();

    int o = t & 31, grp = t >> 5;
    float p = 0.0f;
    #pragma unroll
    for (int k = 0; k < 32; ++k) {
        int cc = grp * 32 + k;
        p += hb[cc] * Wb2[cc * YKS + o];
    }
    part[grp][o] = p;
    __syncthreads();

    if (t < YKS) {
        float s = bb2[t];
        #pragma unroll
        for (int g2 = 0; g2 < 8; ++g2) s += part[g2][t];
        orow[t] += s;
    }
}

// ---------------------------------------------------------------------------
extern "C" void kernel_launch(void* const* d_in, const int* in_sizes, int n_in,
                              void* d_out, int out_size) {
    // metadata order: x, output_size(scalar), W1, b1, W2, b2, Wb1, bb1, Wb2, bb2
    const float* x = (const float*)d_in[0];
    // defensively find W1 (160*256 = 40960 elements): the scalar output_size may
    // or may not appear as an input buffer.
    int idx = 1;
    if (n_in >= 2 && in_sizes[1] != 160 * 256) idx = 2;
    const float* W1  = (const float*)d_in[idx + 0];
    const float* b1  = (const float*)d_in[idx + 1];
    const float* W2  = (const float*)d_in[idx + 2];
    const float* b2  = (const float*)d_in[idx + 3];
    const float* Wb1 = (const float*)d_in[idx + 4];
    const float* bb1 = (const float*)d_in[idx + 5];
    const float* Wb2 = (const float*)d_in[idx + 6];
    const float* bb2 = (const float*)d_in[idx + 7];
    float* out = (float*)d_out;

    k_tables<<<dim3(GX, 3), HID>>>(W1, b1, Wb1, bb1);
    k_A     <<<dim3(BB, GY), HID>>>(x, W1);
    k_U     <<<dim3(BB, YSPLIT), HID>>>(x);
    k_out   <<<BB, HID>>>(W2, b2, out);
    k_bias  <<<dim3(BB, GX), HID>>>(Wb1, Wb2, bb2, out);
}

// round 2
// speedup vs baseline: 1.2180x; 1.2180x over previous
#include <cuda_runtime.h>

// Problem constants (fixed by the dataset)
#define BB    64      // batch
#define INX   1024    // input_size
#define OUTX  1024    // output_size
#define DM    64      // D_MODEL
#define XKS   32
#define YKS   32
#define HID   256
#define GX    32      // gen_x
#define GY    32      // gen_y
#define YSPLIT 8      // split of the y-loop in the reduction kernel
#define BT    4       // batches per k_out block

// Scratch (static device globals -- no allocation allowed)
__device__ float g_PX[GX][HID];        // pe_x(j)@W1[0:64] + b1
__device__ float g_PY[GY][HID];        // pe_y(y)@W1[64:128]
__device__ float g_PEW[GX][HID];       // pe_b(y)@Wb1[32:96] + bb1
__device__ float g_A[BB][GY][HID];     // PX[j] + xchunk(b,j)@W1[128:160]
__device__ float g_U[BB][YSPLIT][HID]; // partial u sums
__device__ float g_S[BB];              // sum_i x[b,i]

// Hardware tanh: single MUFU op (sm_75+), rel err ~2^-11 -- plenty for 1e-3.
__device__ __forceinline__ float tanh_fast(float x) {
    float y;
    asm("tanh.approx.f32 %0, %1;" : "=f"(y) : "f"(x));
    return y;
}

// ---------------------------------------------------------------------------
// K1: batch-independent tables. grid (32, 3), 256 threads.
// ---------------------------------------------------------------------------
__global__ void k_tables(const float* __restrict__ W1, const float* __restrict__ b1,
                         const float* __restrict__ Wb1, const float* __restrict__ bb1) {
    int p     = blockIdx.x;
    int which = blockIdx.y;
    int c     = threadIdx.x;
    __shared__ float pe[DM];
    if (c < DM) {
        int i = c >> 1;
        float f = expf(-(float)i * (9.210340371976184f / 32.0f)); // 10000^{-i/32}
        float ang = (float)p * f;
        pe[c] = (c & 1) ? cosf(ang) : sinf(ang);
    }
    __syncthreads();
    float acc;
    if (which == 0) {
        acc = b1[c];
        #pragma unroll 8
        for (int d = 0; d < DM; ++d) acc += pe[d] * W1[d * HID + c];
        g_PX[p][c] = acc;
    } else if (which == 1) {
        acc = 0.0f;
        #pragma unroll 8
        for (int d = 0; d < DM; ++d) acc += pe[d] * W1[(DM + d) * HID + c];
        g_PY[p][c] = acc;
    } else {
        acc = bb1[c];
        #pragma unroll 8
        for (int d = 0; d < DM; ++d) acc += pe[d] * Wb1[(YKS + d) * HID + c];
        g_PEW[p][c] = acc;
    }
}

// ---------------------------------------------------------------------------
// K2: A[b][j][c] = PX[j][c] + sum_k x[b, 32j+k]*W1[128+k][c]; also S[b].
// grid (64, 32), 256 threads.
// ---------------------------------------------------------------------------
__global__ void k_A(const float* __restrict__ x, const float* __restrict__ W1) {
    int b = blockIdx.x, j = blockIdx.y;
    int c = threadIdx.x;
    __shared__ float xs[XKS];
    if (c < XKS) xs[c] = x[b * INX + j * XKS + c];
    __syncthreads();
    float acc = g_PX[j][c];
    #pragma unroll
    for (int k = 0; k < XKS; ++k) acc += xs[k] * W1[(2 * DM + k) * HID + c];
    g_A[b][j][c] = acc;

    if (j == 0) {  // compute S[b] once per batch
        float s = 0.0f;
        for (int t = c; t < INX; t += HID) s += x[b * INX + t];
        __shared__ float red[HID];
        red[c] = s;
        __syncthreads();
        for (int st = HID / 2; st > 0; st >>= 1) {
            if (c < st) red[c] += red[c + st];
            __syncthreads();
        }
        if (c == 0) g_S[b] = red[0];
    }
}

// ---------------------------------------------------------------------------
// K3 (MUFU-bound): partial u[b][yg][c] = sum over y in [4yg,4yg+4), j in [0,32)
//   of x[b, 32y+j] * tanh(A[b][j][c] + PY[y][c]).
// grid (64, 8), 256 threads. A row cached in 32 registers per thread.
// ---------------------------------------------------------------------------
__global__ void k_U(const float* __restrict__ x) {
    int b = blockIdx.x, yg = blockIdx.y;
    int c = threadIdx.x;
    __shared__ float xs[128];
    int base = b * INX + yg * 128;
    if (c < 128) xs[c] = x[base + c];
    __syncthreads();

    float a[GY];
    #pragma unroll
    for (int jj = 0; jj < GY; ++jj) a[jj] = g_A[b][jj][c];

    float u = 0.0f;
    #pragma unroll
    for (int y4 = 0; y4 < 4; ++y4) {
        float py = g_PY[yg * 4 + y4][c];
        #pragma unroll
        for (int jj = 0; jj < GY; ++jj) {
            u += xs[y4 * 32 + jj] * tanh_fast(a[jj] + py);
        }
    }
    g_U[b][yg][c] = u;
}

// ---------------------------------------------------------------------------
// K4: out[b][o] = sum_c u[b][c]*W2[c][o] + S[b]*b2[o].
// grid (BB/BT=16, OUTX/256=4), 256 threads. Each block: 4 batches x 256 outs,
// reads its W2 quarter once for all 4 batches (W2 reuse x4).
// ---------------------------------------------------------------------------
__global__ void k_out(const float* __restrict__ W2, const float* __restrict__ b2,
                      float* __restrict__ out) {
    int b0 = blockIdx.x * BT;
    int o  = blockIdx.y * 256 + threadIdx.x;
    int t  = threadIdx.x;
    __shared__ float us[BT][HID];

    #pragma unroll
    for (int bi = 0; bi < BT; ++bi) {
        float u = 0.0f;
        #pragma unroll
        for (int p = 0; p < YSPLIT; ++p) u += g_U[b0 + bi][p][t];
        us[bi][t] = u;
    }
    __syncthreads();

    float bb2v = b2[o];
    float a0 = g_S[b0 + 0] * bb2v;
    float a1 = g_S[b0 + 1] * bb2v;
    float a2 = g_S[b0 + 2] * bb2v;
    float a3 = g_S[b0 + 3] * bb2v;
    #pragma unroll 8
    for (int cc = 0; cc < HID; ++cc) {
        float w = W2[cc * OUTX + o];
        a0 += us[0][cc] * w;
        a1 += us[1][cc] * w;
        a2 += us[2][cc] * w;
        a3 += us[3][cc] * w;
    }
    out[(b0 + 0) * OUTX + o] = a0;
    out[(b0 + 1) * OUTX + o] = a1;
    out[(b0 + 2) * OUTX + o] = a2;
    out[(b0 + 3) * OUTX + o] = a3;
}

// ---------------------------------------------------------------------------
// K5: bias hypernetwork, added in place. grid (64, 32), 256 threads.
// ---------------------------------------------------------------------------
__global__ void k_bias(const float* __restrict__ Wb1, const float* __restrict__ Wb2,
                       const float* __restrict__ bb2, float* __restrict__ out) {
    int b = blockIdx.x, y = blockIdx.y;
    int t = threadIdx.x;
    __shared__ float oc[YKS];
    __shared__ float hb[HID];
    __shared__ float part[8][YKS];
    float* orow = out + b * OUTX + y * YKS;
    if (t < YKS) oc[t] = orow[t];
    __syncthreads();

    float acc = g_PEW[y][t];
    #pragma unroll
    for (int k = 0; k < YKS; ++k) acc += oc[k] * Wb1[k * HID + t];
    hb[t] = tanh_fast(acc);
    __syncthreads();

    int o = t & 31, grp = t >> 5;
    float p = 0.0f;
    #pragma unroll
    for (int k = 0; k < 32; ++k) {
        int cc = grp * 32 + k;
        p += hb[cc] * Wb2[cc * YKS + o];
    }
    part[grp][o] = p;
    __syncthreads();

    if (t < YKS) {
        float s = bb2[t];
        #pragma unroll
        for (int g2 = 0; g2 < 8; ++g2) s += part[g2][t];
        orow[t] += s;
    }
}

// ---------------------------------------------------------------------------
extern "C" void kernel_launch(void* const* d_in, const int* in_sizes, int n_in,
                              void* d_out, int out_size) {
    const float* x = (const float*)d_in[0];
    int idx = 1;
    if (n_in >= 2 && in_sizes[1] != 160 * 256) idx = 2;
    const float* W1  = (const float*)d_in[idx + 0];
    const float* b1  = (const float*)d_in[idx + 1];
    const float* W2  = (const float*)d_in[idx + 2];
    const float* b2  = (const float*)d_in[idx + 3];
    const float* Wb1 = (const float*)d_in[idx + 4];
    const float* bb1 = (const float*)d_in[idx + 5];
    const float* Wb2 = (const float*)d_in[idx + 6];
    const float* bb2 = (const float*)d_in[idx + 7];
    float* out = (float*)d_out;

    k_tables<<<dim3(GX, 3), HID>>>(W1, b1, Wb1, bb1);
    k_A     <<<dim3(BB, GY), HID>>>(x, W1);
    k_U     <<<dim3(BB, YSPLIT), HID>>>(x);
    k_out   <<<dim3(BB / BT, OUTX / 256), HID>>>(W2, b2, out);
    k_bias  <<<dim3(BB, GX), HID>>>(Wb1, Wb2, bb2, out);
}

// round 3
// speedup vs baseline: 1.6776x; 1.3773x over previous
#include <cuda_runtime.h>

// Problem constants (fixed by the dataset)
#define BB    64      // batch
#define INX   1024    // input_size
#define OUTX  1024    // output_size
#define DM    64      // D_MODEL
#define XKS   32
#define YKS   32
#define HID   256
#define GX    32      // gen_x
#define GY    32      // gen_y
#define YSPLIT 8      // split of the y-loop in k_U
#define BT    4       // batches per k_out block
#define CSPLIT 4      // cc-splits in k_out (HID/CSPLIT = 64 per block)

// Scratch (static device globals -- no allocation allowed)
__device__ float g_PX[GX][HID];          // pe_x(j)@W1[0:64] + b1
__device__ float g_PY[GY][HID];          // pe_y(y)@W1[64:128]
__device__ float g_PEW[GX][HID];         // pe_b(y)@Wb1[32:96] + bb1
__device__ float g_A[BB][GY][HID];       // PX[j] + xchunk(b,j)@W1[128:160]
__device__ float g_U[BB][YSPLIT][HID];   // partial u sums
__device__ float g_S[BB];                // sum_i x[b,i]
__device__ float g_outp[CSPLIT][BB][OUTX]; // partial out sums

// Hardware tanh: single MUFU op, rel err ~2^-11 -- plenty for 1e-3.
__device__ __forceinline__ float tanh_fast(float x) {
    float y;
    asm("tanh.approx.f32 %0, %1;" : "=f"(y) : "f"(x));
    return y;
}

// ---------------------------------------------------------------------------
// K1: batch-independent tables. grid (32, 3), 256 threads.
// ---------------------------------------------------------------------------
__global__ void k_tables(const float* __restrict__ W1, const float* __restrict__ b1,
                         const float* __restrict__ Wb1, const float* __restrict__ bb1) {
    int p     = blockIdx.x;
    int which = blockIdx.y;
    int c     = threadIdx.x;
    __shared__ float pe[DM];
    if (c < DM) {
        int i = c >> 1;
        float f = expf(-(float)i * (9.210340371976184f / 32.0f)); // 10000^{-i/32}
        float ang = (float)p * f;
        pe[c] = (c & 1) ? cosf(ang) : sinf(ang);
    }
    __syncthreads();
    float acc;
    if (which == 0) {
        acc = b1[c];
        #pragma unroll 8
        for (int d = 0; d < DM; ++d) acc += pe[d] * W1[d * HID + c];
        g_PX[p][c] = acc;
    } else if (which == 1) {
        acc = 0.0f;
        #pragma unroll 8
        for (int d = 0; d < DM; ++d) acc += pe[d] * W1[(DM + d) * HID + c];
        g_PY[p][c] = acc;
    } else {
        acc = bb1[c];
        #pragma unroll 8
        for (int d = 0; d < DM; ++d) acc += pe[d] * Wb1[(YKS + d) * HID + c];
        g_PEW[p][c] = acc;
    }
}

// ---------------------------------------------------------------------------
// K2: A[b][j][c] = PX[j][c] + sum_k x[b, 32j+k]*W1[128+k][c]; also S[b].
// grid (64, 32), 256 threads.
// ---------------------------------------------------------------------------
__global__ void k_A(const float* __restrict__ x, const float* __restrict__ W1) {
    int b = blockIdx.x, j = blockIdx.y;
    int c = threadIdx.x;
    __shared__ float xs[XKS];
    if (c < XKS) xs[c] = x[b * INX + j * XKS + c];
    __syncthreads();
    float acc = g_PX[j][c];
    #pragma unroll
    for (int k = 0; k < XKS; ++k) acc += xs[k] * W1[(2 * DM + k) * HID + c];
    g_A[b][j][c] = acc;

    if (j == 0) {  // compute S[b] once per batch
        float s = 0.0f;
        for (int t = c; t < INX; t += HID) s += x[b * INX + t];
        __shared__ float red[HID];
        red[c] = s;
        __syncthreads();
        for (int st = HID / 2; st > 0; st >>= 1) {
            if (c < st) red[c] += red[c + st];
            __syncthreads();
        }
        if (c == 0) g_S[b] = red[0];
    }
}

// ---------------------------------------------------------------------------
// K3 (MUFU-bound): partial u[b][yg][c] = sum over y in [4yg,4yg+4), j in [0,32)
//   of x[b, 32y+j] * tanh(A[b][j][c] + PY[y][c]).
// grid (64, 8), 256 threads. A row cached in 32 registers per thread.
// ---------------------------------------------------------------------------
__global__ void k_U(const float* __restrict__ x) {
    int b = blockIdx.x, yg = blockIdx.y;
    int c = threadIdx.x;
    __shared__ float xs[128];
    int base = b * INX + yg * 128;
    if (c < 128) xs[c] = x[base + c];
    __syncthreads();

    float a[GY];
    #pragma unroll
    for (int jj = 0; jj < GY; ++jj) a[jj] = g_A[b][jj][c];

    float u = 0.0f;
    #pragma unroll
    for (int y4 = 0; y4 < 4; ++y4) {
        float py = g_PY[yg * 4 + y4][c];
        #pragma unroll
        for (int jj = 0; jj < GY; ++jj) {
            u += xs[y4 * 32 + jj] * tanh_fast(a[jj] + py);
        }
    }
    g_U[b][yg][c] = u;
}

// ---------------------------------------------------------------------------
// K4: partial out. grid (BB/BT=16, OUTX/256=4, CSPLIT=4) = 256 blocks.
//   g_outp[sp][b][o] = sum_{cc in sp-chunk} u[b][cc]*W2[cc][o]  (+S[b]*b2[o] on sp0)
// Each block: 4 batches x 256 outs x 64 cc. Fully unrolled -> high MLP.
// ---------------------------------------------------------------------------
__global__ void k_out(const float* __restrict__ W2, const float* __restrict__ b2) {
    int b0 = blockIdx.x * BT;
    int o  = blockIdx.y * 256 + threadIdx.x;
    int sp = blockIdx.z;
    int t  = threadIdx.x;
    int cc0 = sp * (HID / CSPLIT);

    // us[bi][cc] for this chunk: thread t handles (bi = t>>6, cc = t&63)
    __shared__ float us[BT][HID / CSPLIT];
    {
        int bi = t >> 6, cc = t & 63;
        float u = 0.0f;
        #pragma unroll
        for (int p = 0; p < YSPLIT; ++p) u += g_U[b0 + bi][p][cc0 + cc];
        us[bi][cc] = u;
    }
    __syncthreads();

    float a0, a1, a2, a3;
    if (sp == 0) {
        float bb2v = b2[o];
        a0 = g_S[b0 + 0] * bb2v;
        a1 = g_S[b0 + 1] * bb2v;
        a2 = g_S[b0 + 2] * bb2v;
        a3 = g_S[b0 + 3] * bb2v;
    } else {
        a0 = a1 = a2 = a3 = 0.0f;
    }
    #pragma unroll 16
    for (int cc = 0; cc < HID / CSPLIT; ++cc) {
        float w = W2[(cc0 + cc) * OUTX + o];
        a0 += us[0][cc] * w;
        a1 += us[1][cc] * w;
        a2 += us[2][cc] * w;
        a3 += us[3][cc] * w;
    }
    g_outp[sp][b0 + 0][o] = a0;
    g_outp[sp][b0 + 1][o] = a1;
    g_outp[sp][b0 + 2][o] = a2;
    g_outp[sp][b0 + 3][o] = a3;
}

// ---------------------------------------------------------------------------
// K5: sum partials + bias hypernetwork; writes FINAL output.
// grid (64, 32), 256 threads.
// ---------------------------------------------------------------------------
__global__ void k_bias(const float* __restrict__ Wb1, const float* __restrict__ Wb2,
                       const float* __restrict__ bb2, float* __restrict__ out) {
    int b = blockIdx.x, y = blockIdx.y;
    int t = threadIdx.x;
    __shared__ float oc[YKS];
    __shared__ float hb[HID];
    __shared__ float part[8][YKS];
    if (t < YKS) {
        int o = y * YKS + t;
        float v = 0.0f;
        #pragma unroll
        for (int sp = 0; sp < CSPLIT; ++sp) v += g_outp[sp][b][o];
        oc[t] = v;
    }
    __syncthreads();

    float acc = g_PEW[y][t];
    #pragma unroll
    for (int k = 0; k < YKS; ++k) acc += oc[k] * Wb1[k * HID + t];
    hb[t] = tanh_fast(acc);
    __syncthreads();

    int o = t & 31, grp = t >> 5;
    float p = 0.0f;
    #pragma unroll
    for (int k = 0; k < 32; ++k) {
        int cc = grp * 32 + k;
        p += hb[cc] * Wb2[cc * YKS + o];
    }
    part[grp][o] = p;
    __syncthreads();

    if (t < YKS) {
        float s = bb2[t];
        #pragma unroll
        for (int g2 = 0; g2 < 8; ++g2) s += part[g2][t];
        out[b * OUTX + y * YKS + t] = oc[t] + s;
    }
}

// ---------------------------------------------------------------------------
extern "C" void kernel_launch(void* const* d_in, const int* in_sizes, int n_in,
                              void* d_out, int out_size) {
    const float* x = (const float*)d_in[0];
    int idx = 1;
    if (n_in >= 2 && in_sizes[1] != 160 * 256) idx = 2;
    const float* W1  = (const float*)d_in[idx + 0];
    const float* b1  = (const float*)d_in[idx + 1];
    const float* W2  = (const float*)d_in[idx + 2];
    const float* b2  = (const float*)d_in[idx + 3];
    const float* Wb1 = (const float*)d_in[idx + 4];
    const float* bb1 = (const float*)d_in[idx + 5];
    const float* Wb2 = (const float*)d_in[idx + 6];
    const float* bb2 = (const float*)d_in[idx + 7];
    float* out = (float*)d_out;

    k_tables<<<dim3(GX, 3), HID>>>(W1, b1, Wb1, bb1);
    k_A     <<<dim3(BB, GY), HID>>>(x, W1);
    k_U     <<<dim3(BB, YSPLIT), HID>>>(x);
    k_out   <<<dim3(BB / BT, OUTX / 256, CSPLIT), HID>>>(W2, b2);
    k_bias  <<<dim3(BB, GX), HID>>>(Wb1, Wb2, bb2, out);
}

// round 4
// speedup vs baseline: 1.8119x; 1.0800x over previous
#include <cuda_runtime.h>

// Problem constants (fixed by the dataset)
#define BB    64      // batch
#define INX   1024    // input_size
#define OUTX  1024    // output_size
#define DM    64      // D_MODEL
#define XKS   32
#define YKS   32
#define HID   256
#define GX    32      // gen_x
#define GY    32      // gen_y
#define YSPLIT 8      // split of the y-loop in k_U
#define BT    4       // batches per k_out block
#define CSPLIT 16     // cc-splits in k_out
#define CS    (HID / CSPLIT)   // 16 cc per block

// Scratch (static device globals -- no allocation allowed)
__device__ float g_PX[GX][HID];            // pe_x(j)@W1[0:64] + b1
__device__ float g_PY[GY][HID];            // pe_y(y)@W1[64:128]
__device__ float g_PEW[GX][HID];           // pe_b(y)@Wb1[32:96] + bb1
__device__ float g_A[BB][GY][HID];         // PX[j] + xchunk(b,j)@W1[128:160]
__device__ float g_U[BB][YSPLIT][HID];     // partial u sums
__device__ float g_S[BB];                  // sum_i x[b,i]
__device__ float g_outp[CSPLIT][BB][OUTX]; // partial out sums (4 MB)

// Hardware tanh: single MUFU op, rel err ~2^-11 -- plenty for 1e-3.
__device__ __forceinline__ float tanh_fast(float x) {
    float y;
    asm("tanh.approx.f32 %0, %1;" : "=f"(y) : "f"(x));
    return y;
}

// ---------------------------------------------------------------------------
// K1: batch-independent tables. grid (32, 3), 256 threads.
// ---------------------------------------------------------------------------
__global__ void k_tables(const float* __restrict__ W1, const float* __restrict__ b1,
                         const float* __restrict__ Wb1, const float* __restrict__ bb1) {
    int p     = blockIdx.x;
    int which = blockIdx.y;
    int c     = threadIdx.x;
    __shared__ float pe[DM];
    if (c < DM) {
        int i = c >> 1;
        float f = expf(-(float)i * (9.210340371976184f / 32.0f)); // 10000^{-i/32}
        float ang = (float)p * f;
        pe[c] = (c & 1) ? cosf(ang) : sinf(ang);
    }
    __syncthreads();
    float acc;
    if (which == 0) {
        acc = b1[c];
        #pragma unroll 8
        for (int d = 0; d < DM; ++d) acc += pe[d] * W1[d * HID + c];
        g_PX[p][c] = acc;
    } else if (which == 1) {
        acc = 0.0f;
        #pragma unroll 8
        for (int d = 0; d < DM; ++d) acc += pe[d] * W1[(DM + d) * HID + c];
        g_PY[p][c] = acc;
    } else {
        acc = bb1[c];
        #pragma unroll 8
        for (int d = 0; d < DM; ++d) acc += pe[d] * Wb1[(YKS + d) * HID + c];
        g_PEW[p][c] = acc;
    }
}

// ---------------------------------------------------------------------------
// K2: A[b][j][c] = PX[j][c] + sum_k x[b, 32j+k]*W1[128+k][c]; also S[b].
// grid (64, 32), 256 threads.
// ---------------------------------------------------------------------------
__global__ void k_A(const float* __restrict__ x, const float* __restrict__ W1) {
    int b = blockIdx.x, j = blockIdx.y;
    int c = threadIdx.x;
    __shared__ float xs[XKS];
    if (c < XKS) xs[c] = x[b * INX + j * XKS + c];
    __syncthreads();
    float acc = g_PX[j][c];
    #pragma unroll
    for (int k = 0; k < XKS; ++k) acc += xs[k] * W1[(2 * DM + k) * HID + c];
    g_A[b][j][c] = acc;

    if (j == 0) {  // compute S[b] once per batch
        float s = 0.0f;
        for (int t = c; t < INX; t += HID) s += x[b * INX + t];
        __shared__ float red[HID];
        red[c] = s;
        __syncthreads();
        for (int st = HID / 2; st > 0; st >>= 1) {
            if (c < st) red[c] += red[c + st];
            __syncthreads();
        }
        if (c == 0) g_S[b] = red[0];
    }
}

// ---------------------------------------------------------------------------
// K3 (MUFU-bound): partial u[b][yg][c] = sum over y in [4yg,4yg+4), j in [0,32)
//   of x[b, 32y+j] * tanh(A[b][j][c] + PY[y][c]).
// grid (64, 8), 256 threads. A row cached in 32 registers per thread.
// ---------------------------------------------------------------------------
__global__ void k_U(const float* __restrict__ x) {
    int b = blockIdx.x, yg = blockIdx.y;
    int c = threadIdx.x;
    __shared__ float xs[128];
    int base = b * INX + yg * 128;
    if (c < 128) xs[c] = x[base + c];
    __syncthreads();

    float a[GY];
    #pragma unroll
    for (int jj = 0; jj < GY; ++jj) a[jj] = g_A[b][jj][c];

    float u = 0.0f;
    #pragma unroll
    for (int y4 = 0; y4 < 4; ++y4) {
        float py = g_PY[yg * 4 + y4][c];
        #pragma unroll
        for (int jj = 0; jj < GY; ++jj) {
            u += xs[y4 * 32 + jj] * tanh_fast(a[jj] + py);
        }
    }
    g_U[b][yg][c] = u;
}

// ---------------------------------------------------------------------------
// K4: partial out, vectorized. grid (BB/BT=16, CSPLIT=16) = 256 blocks,
// 256 threads. Thread t owns outputs [4t, 4t+4) via float4 LDG.128 of W2;
// 16 fully independent loads per thread -> one latency exposure.
//   g_outp[sp][b][o] = sum_{cc in sp-chunk} u[b][cc]*W2[cc][o] (+S[b]*b2[o] @sp0)
// ---------------------------------------------------------------------------
__global__ void k_out(const float* __restrict__ W2, const float* __restrict__ b2) {
    int b0  = blockIdx.x * BT;
    int sp  = blockIdx.y;
    int t   = threadIdx.x;
    int o   = t * 4;
    int cc0 = sp * CS;

    __shared__ float us[BT][CS];
    if (t < BT * CS) {   // 64 threads build the u chunk
        int bi = t / CS, cc = t % CS;
        float u = 0.0f;
        #pragma unroll
        for (int p = 0; p < YSPLIT; ++p) u += g_U[b0 + bi][p][cc0 + cc];
        us[bi][cc] = u;
    }
    __syncthreads();

    float4 acc[BT];
    if (sp == 0) {
        float4 bv = *(const float4*)(b2 + o);
        #pragma unroll
        for (int bi = 0; bi < BT; ++bi) {
            float s = g_S[b0 + bi];
            acc[bi] = make_float4(s * bv.x, s * bv.y, s * bv.z, s * bv.w);
        }
    } else {
        #pragma unroll
        for (int bi = 0; bi < BT; ++bi) acc[bi] = make_float4(0.f, 0.f, 0.f, 0.f);
    }

    #pragma unroll
    for (int cc = 0; cc < CS; ++cc) {
        float4 w = *(const float4*)(W2 + (cc0 + cc) * OUTX + o);
        #pragma unroll
        for (int bi = 0; bi < BT; ++bi) {
            float uv = us[bi][cc];
            acc[bi].x += uv * w.x;
            acc[bi].y += uv * w.y;
            acc[bi].z += uv * w.z;
            acc[bi].w += uv * w.w;
        }
    }

    #pragma unroll
    for (int bi = 0; bi < BT; ++bi)
        *(float4*)(&g_outp[sp][b0 + bi][o]) = acc[bi];
}

// ---------------------------------------------------------------------------
// K5: sum 16 partials (parallel 2-stage reduce) + bias hypernetwork;
// writes FINAL output. grid (64, 32), 256 threads.
// ---------------------------------------------------------------------------
__global__ void k_bias(const float* __restrict__ Wb1, const float* __restrict__ Wb2,
                       const float* __restrict__ bb2, float* __restrict__ out) {
    int b = blockIdx.x, y = blockIdx.y;
    int t = threadIdx.x;
    __shared__ float ocp[8][YKS];
    __shared__ float oc[YKS];
    __shared__ float hb[HID];
    __shared__ float part[8][YKS];

    {   // stage 1: 256 threads, 2 partial loads each
        int s2 = t >> 5, o = t & 31;
        int oi = y * YKS + o;
        ocp[s2][o] = g_outp[2 * s2][b][oi] + g_outp[2 * s2 + 1][b][oi];
    }
    __syncthreads();
    if (t < YKS) {   // stage 2
        float v = 0.0f;
        #pragma unroll
        for (int s2 = 0; s2 < 8; ++s2) v += ocp[s2][t];
        oc[t] = v;
    }
    __syncthreads();

    float acc = g_PEW[y][t];
    #pragma unroll
    for (int k = 0; k < YKS; ++k) acc += oc[k] * Wb1[k * HID + t];
    hb[t] = tanh_fast(acc);
    __syncthreads();

    int o = t & 31, grp = t >> 5;
    float p = 0.0f;
    #pragma unroll
    for (int k = 0; k < 32; ++k) {
        int cc = grp * 32 + k;
        p += hb[cc] * Wb2[cc * YKS + o];
    }
    part[grp][o] = p;
    __syncthreads();

    if (t < YKS) {
        float s = bb2[t];
        #pragma unroll
        for (int g2 = 0; g2 < 8; ++g2) s += part[g2][t];
        out[b * OUTX + y * YKS + t] = oc[t] + s;
    }
}

// ---------------------------------------------------------------------------
extern "C" void kernel_launch(void* const* d_in, const int* in_sizes, int n_in,
                              void* d_out, int out_size) {
    const float* x = (const float*)d_in[0];
    int idx = 1;
    if (n_in >= 2 && in_sizes[1] != 160 * 256) idx = 2;
    const float* W1  = (const float*)d_in[idx + 0];
    const float* b1  = (const float*)d_in[idx + 1];
    const float* W2  = (const float*)d_in[idx + 2];
    const float* b2  = (const float*)d_in[idx + 3];
    const float* Wb1 = (const float*)d_in[idx + 4];
    const float* bb1 = (const float*)d_in[idx + 5];
    const float* Wb2 = (const float*)d_in[idx + 6];
    const float* bb2 = (const float*)d_in[idx + 7];
    float* out = (float*)d_out;

    k_tables<<<dim3(GX, 3), HID>>>(W1, b1, Wb1, bb1);
    k_A     <<<dim3(BB, GY), HID>>>(x, W1);
    k_U     <<<dim3(BB, YSPLIT), HID>>>(x);
    k_out   <<<dim3(BB / BT, CSPLIT), HID>>>(W2, b2);
    k_bias  <<<dim3(BB, GX), HID>>>(Wb1, Wb2, bb2, out);
}